// round 9
// baseline (speedup 1.0000x reference)
#include <cuda_runtime.h>

// ---------------------------------------------------------------------------
// Model_19095424598065 v9 : algebraically reduced graph-spectral net.
// vs v8: (1) revert ILP split (measured +15us), (2) mode_gemm pairs the
// f32x2 lanes over K (even/odd partial sums) so the x operand is a raw u64
// read from the scalar XF layout and M comes pre-paired from precompute —
// zero operand-marshalling MOVs in the hot loop, (3) Um dup-pair smem for
// stages C/E (16 MOV/node -> 2 uniform LDS/node).
// ---------------------------------------------------------------------------

typedef unsigned long long u64t;

#define NT 256
#define TT 8

// M stored K-pair-transposed: d_M[k][ip][2c+e] = M_k[2*ip+e][c]  (u64 pairs)
__device__ float d_M0[8 * 128 * 128];
__device__ float d_M2[8 * 128 * 128];
__device__ float d_tv[8];
__device__ float d_b1[128];
__device__ float d_b3[128];

// ------------------------------ helpers ------------------------------------
static __device__ __forceinline__ u64t dup2(float x) {
    u64t r; asm("mov.b64 %0, {%1, %1};" : "=l"(r) : "f"(x)); return r;
}
static __device__ __forceinline__ u64t pack2(float a, float b) {
    u64t r; asm("mov.b64 %0, {%1, %2};" : "=l"(r) : "f"(a), "f"(b)); return r;
}
static __device__ __forceinline__ void unpack2(u64t v, float& a, float& b) {
    asm("mov.b64 {%0, %1}, %2;" : "=f"(a), "=f"(b) : "l"(v));
}
static __device__ __forceinline__ void fma2(u64t& d, u64t a, u64t b) {
    asm("fma.rn.f32x2 %0, %1, %2, %3;" : "=l"(d) : "l"(a), "l"(b), "l"(d));
}
static __device__ __forceinline__ u64t add2(u64t a, u64t b) {
    u64t r; asm("add.rn.f32x2 %0, %1, %2;" : "=l"(r) : "l"(a), "l"(b)); return r;
}
static __device__ __forceinline__ float fold2(u64t v) {
    float a, b; unpack2(v, a, b); return a + b;
}

// --------------------------- fused precompute ------------------------------
// 256 blocks: b<128 -> M0 row b; b>=128 -> M2 row b-128. lam computed locally.
__global__ void pre_kernel(const float* __restrict__ U, const float* __restrict__ adj,
                           const float* __restrict__ w0, const float* __restrict__ w2,
                           const float* __restrict__ Ws1, const float* __restrict__ Wn1,
                           const float* __restrict__ Ws3, const float* __restrict__ Wn3,
                           const float* __restrict__ bs1, const float* __restrict__ bn1,
                           const float* __restrict__ bs3, const float* __restrict__ bn3)
{
    __shared__ float sw[1024];
    __shared__ float spart[128];
    __shared__ float slam[8];
    const int b = blockIdx.x, c = threadIdx.x;
    const int which = b >> 7, i = b & 127;
    const float* w  = which ? w2  : w0;
    const float* Ws = which ? Ws3 : Ws1;
    const float* Wn = which ? Wn3 : Wn1;

    {
        const int k = c >> 4, s = c & 15;
        float part = 0.f;
        for (int n = s; n < 64; n += 16) {
            float g = 0.f;
            for (int m = 0; m < 64; m++) g += adj[n * 64 + m] * U[m * 64 + k];
            part += U[n * 64 + k] * g;
        }
        spart[c] = part;
    }
    for (int idx = c; idx < 1024; idx += 128) sw[idx] = w[i * 1024 + idx];
    __syncthreads();
    if (c < 8) {
        float lam = 0.f;
        for (int s = 0; s < 16; s++) lam += spart[c * 16 + s];
        slam[c] = lam;
    }
    if (b == 0) {
        if (c < 128) { d_b1[c] = bs1[c] + bn1[c]; d_b3[c] = bs3[c] + bn3[c]; }
        if (c < 8) {
            float ts = 0.f;
            for (int n = 0; n < 64; n++) ts += U[n * 64 + c];
            d_tv[c] = ts;
        }
    }
    __syncthreads();

    float lam[8], acc[8];
#pragma unroll
    for (int k = 0; k < 8; k++) { lam[k] = slam[k]; acc[k] = 0.f; }
#pragma unroll 2
    for (int j = 0; j < 128; j++) {
        float ws = __ldg(Ws + j * 128 + c);
        float wn = __ldg(Wn + j * 128 + c);
#pragma unroll
        for (int k = 0; k < 8; k++)
            acc[k] += sw[j * 8 + k] * fmaf(lam[k], wn, ws);
    }
    // K-pair-transposed store: [k][i>>1][2c + (i&1)]
    float* M = which ? d_M2 : d_M0;
    const int off = (i >> 1) * 256 + 2 * c + (i & 1);
#pragma unroll
    for (int k = 0; k < 8; k++) M[k * 16384 + off] = acc[k];
}

// ------------------------------- main kernel -------------------------------
// smem (floats):
//  sFX  [0    , 8192 )  XF/F in place [t][k][c] (scalar layout)
//  sUmD [8192 , 9216 )  Um dup pairs: row n = 16 floats (u_k,u_k)x8
//  sUm  [9216 , 9728 )  Um scalar (stage A only)
//  sWp  [9728 , 10752)  Wp[p][c]
//  sV   [10752, 11776)  bp|b1|b3|g1|be1|g3|be3|bo(8)|tv(8)
//  sY   [11776, 12288)  stage-A y[t][k][p]
//  sWoB [12288, 13312)  Wo pairs, per-lane swizzled (512 u64)
#define O_FX  0
#define O_UMD 8192
#define O_UM  9216
#define O_WP  9728
#define O_V   10752
#define O_Y   11776
#define O_WOB 12288
#define SMEMF 13312

// F[t,k,:] = XF[t,k,:] @ M_k (K=128), in place. Warp k owns mode k's rows.
// f32x2 lanes paired over K: acc[t][c] = (sum over even K, sum over odd K).
// x operand = raw u64 from scalar XF; M pre-paired -> zero MOVs in loop.
static __device__ __forceinline__ void mode_gemm(const float* __restrict__ M,
                                                 float* sFX, int tid)
{
    const int k = tid >> 5, lane = tid & 31;
    const ulonglong2* Mp = (const ulonglong2*)(M + k * 16384);  // 64 u2 per ip-row
    u64t acc[TT][4];
#pragma unroll
    for (int t = 0; t < TT; t++)
#pragma unroll
        for (int q = 0; q < 4; q++) acc[t][q] = 0ull;

#pragma unroll 2
    for (int i4 = 0; i4 < 32; i4++) {
        // ip = 2*i4, 2*i4+1 ; lane's columns c = 4*lane..4*lane+3
        ulonglong2 m0 = __ldg(&Mp[(2 * i4)     * 64 + 2 * lane]);      // ip0, c0 c1
        ulonglong2 m1 = __ldg(&Mp[(2 * i4)     * 64 + 2 * lane + 1]);  // ip0, c2 c3
        ulonglong2 m2 = __ldg(&Mp[(2 * i4 + 1) * 64 + 2 * lane]);      // ip1, c0 c1
        ulonglong2 m3 = __ldg(&Mp[(2 * i4 + 1) * 64 + 2 * lane + 1]);  // ip1, c2 c3
#pragma unroll
        for (int t = 0; t < TT; t++) {
            // (x_{4i4},x_{4i4+1}) and (x_{4i4+2},x_{4i4+3}) — uniform broadcast
            ulonglong2 xq = *(const ulonglong2*)(sFX + (t * 8 + k) * 128 + 4 * i4);
            fma2(acc[t][0], xq.x, m0.x); fma2(acc[t][1], xq.x, m0.y);
            fma2(acc[t][2], xq.x, m1.x); fma2(acc[t][3], xq.x, m1.y);
            fma2(acc[t][0], xq.y, m2.x); fma2(acc[t][1], xq.y, m2.y);
            fma2(acc[t][2], xq.y, m3.x); fma2(acc[t][3], xq.y, m3.y);
        }
    }
#pragma unroll
    for (int t = 0; t < TT; t++) {
        float4 f;
        f.x = fold2(acc[t][0]); f.y = fold2(acc[t][1]);
        f.z = fold2(acc[t][2]); f.w = fold2(acc[t][3]);
        *(float4*)(sFX + (t * 8 + k) * 128 + 4 * lane) = f;
    }
}

// Stage C, one warp = one tile t: o = Um@F + b1 -> LN -> relu -> xf2 = Um^T h.
// Um read as dup pairs (uniform LDS.128, zero MOVs).
static __device__ __forceinline__ void tile_stageC(float* sFX, const float* sUmD,
                                                   const float* sV, int t, int lane)
{
    u64t Fr0[8], Fr1[8];
#pragma unroll
    for (int k = 0; k < 8; k++) {
        float4 f = *(const float4*)(sFX + (t * 8 + k) * 128 + 4 * lane);
        Fr0[k] = pack2(f.x, f.y); Fr1[k] = pack2(f.z, f.w);
    }
    const float4 bq = *(const float4*)(sV + 128 + 4 * lane);
    const float4 gq = *(const float4*)(sV + 384 + 4 * lane);
    const float4 eq = *(const float4*)(sV + 512 + 4 * lane);
    const u64t b01 = pack2(bq.x, bq.y), b23 = pack2(bq.z, bq.w);

    u64t X20[8], X21[8];
#pragma unroll
    for (int k = 0; k < 8; k++) { X20[k] = 0ull; X21[k] = 0ull; }

#pragma unroll 4
    for (int n = 0; n < 64; n++) {
        ulonglong2 uA = *(const ulonglong2*)(sUmD + n * 16);       // (u0,u0),(u1,u1)
        ulonglong2 uB = *(const ulonglong2*)(sUmD + n * 16 + 4);   // u2,u3
        ulonglong2 uC = *(const ulonglong2*)(sUmD + n * 16 + 8);   // u4,u5
        ulonglong2 uD = *(const ulonglong2*)(sUmD + n * 16 + 12);  // u6,u7
        u64t uk[8] = {uA.x, uA.y, uB.x, uB.y, uC.x, uC.y, uD.x, uD.y};
        u64t o0 = b01, o1 = b23;
#pragma unroll
        for (int k = 0; k < 8; k++) { fma2(o0, uk[k], Fr0[k]); fma2(o1, uk[k], Fr1[k]); }
        float a, b, c, d;
        unpack2(o0, a, b); unpack2(o1, c, d);
        float s = a + b + c + d;
        float s2 = a * a + b * b + c * c + d * d;
#pragma unroll
        for (int m = 1; m < 32; m <<= 1) {
            s  += __shfl_xor_sync(0xffffffffu, s, m);
            s2 += __shfl_xor_sync(0xffffffffu, s2, m);
        }
        const float mu = s * 0.0078125f;
        const float rstd = rsqrtf(s2 * 0.0078125f - mu * mu + 1e-5f);
        u64t hA = pack2(fmaxf((a - mu) * rstd * gq.x + eq.x, 0.f),
                        fmaxf((b - mu) * rstd * gq.y + eq.y, 0.f));
        u64t hB = pack2(fmaxf((c - mu) * rstd * gq.z + eq.z, 0.f),
                        fmaxf((d - mu) * rstd * gq.w + eq.w, 0.f));
#pragma unroll
        for (int k = 0; k < 8; k++) { fma2(X20[k], uk[k], hA); fma2(X21[k], uk[k], hB); }
    }
#pragma unroll
    for (int k = 0; k < 8; k++) {
        float a, b, c, d;
        unpack2(X20[k], a, b); unpack2(X21[k], c, d);
        *(float4*)(sFX + (t * 8 + k) * 128 + 4 * lane) = make_float4(a, b, c, d);
    }
}

// Stage E, one warp = one tile: o = Um@F + b3 -> LN -> relu -> out = h@Wo + bo.
static __device__ __forceinline__ void tile_stageE(const float* sFX, const float* sUmD,
                                                   const float* sV, const u64t* sWoB,
                                                   float* __restrict__ outg,
                                                   int t, int lane)
{
    u64t Fr0[8], Fr1[8];
#pragma unroll
    for (int k = 0; k < 8; k++) {
        float4 f = *(const float4*)(sFX + (t * 8 + k) * 128 + 4 * lane);
        Fr0[k] = pack2(f.x, f.y); Fr1[k] = pack2(f.z, f.w);
    }
    const float4 bq = *(const float4*)(sV + 256 + 4 * lane);
    const float4 gq = *(const float4*)(sV + 640 + 4 * lane);
    const float4 eq = *(const float4*)(sV + 768 + 4 * lane);
    const u64t b01 = pack2(bq.x, bq.y), b23 = pack2(bq.z, bq.w);

    // Wo registers: w2[j][q] = (Wo[4l+j][2q], Wo[4l+j][2q+1]); swizzled load
    u64t w2[4][4];
    {
        const int l7 = lane & 7;
#pragma unroll
        for (int u = 0; u < 8; u++) {
            int p = lane * 8 + (u ^ l7);
            u64t A = sWoB[2 * p], B = sWoB[2 * p + 1];
            const int j = u >> 1, qb = (u & 1) * 2;
            w2[j][qb] = A; w2[j][qb + 1] = B;
        }
    }
    const int g = lane >> 3;
    float2 boP = *(const float2*)(sV + 896 + 2 * g);

#pragma unroll 2
    for (int n = 0; n < 64; n++) {
        ulonglong2 uA = *(const ulonglong2*)(sUmD + n * 16);
        ulonglong2 uB = *(const ulonglong2*)(sUmD + n * 16 + 4);
        ulonglong2 uC = *(const ulonglong2*)(sUmD + n * 16 + 8);
        ulonglong2 uD = *(const ulonglong2*)(sUmD + n * 16 + 12);
        u64t uk[8] = {uA.x, uA.y, uB.x, uB.y, uC.x, uC.y, uD.x, uD.y};
        u64t o0 = b01, o1 = b23;
#pragma unroll
        for (int k = 0; k < 8; k++) { fma2(o0, uk[k], Fr0[k]); fma2(o1, uk[k], Fr1[k]); }
        float a, b, c, d;
        unpack2(o0, a, b); unpack2(o1, c, d);
        float s = a + b + c + d;
        float s2 = a * a + b * b + c * c + d * d;
#pragma unroll
        for (int m = 1; m < 32; m <<= 1) {
            s  += __shfl_xor_sync(0xffffffffu, s, m);
            s2 += __shfl_xor_sync(0xffffffffu, s2, m);
        }
        const float mu = s * 0.0078125f;
        const float rstd = rsqrtf(s2 * 0.0078125f - mu * mu + 1e-5f);
        float h0 = fmaxf((a - mu) * rstd * gq.x + eq.x, 0.f);
        float h1 = fmaxf((b - mu) * rstd * gq.y + eq.y, 0.f);
        float h2 = fmaxf((c - mu) * rstd * gq.z + eq.z, 0.f);
        float h3 = fmaxf((d - mu) * rstd * gq.w + eq.w, 0.f);

        u64t acc2[4] = {0ull, 0ull, 0ull, 0ull};
        u64t hb;
        hb = dup2(h0);
#pragma unroll
        for (int q = 0; q < 4; q++) fma2(acc2[q], hb, w2[0][q]);
        hb = dup2(h1);
#pragma unroll
        for (int q = 0; q < 4; q++) fma2(acc2[q], hb, w2[1][q]);
        hb = dup2(h2);
#pragma unroll
        for (int q = 0; q < 4; q++) fma2(acc2[q], hb, w2[2][q]);
        hb = dup2(h3);
#pragma unroll
        for (int q = 0; q < 4; q++) fma2(acc2[q], hb, w2[3][q]);

#pragma unroll
        for (int q = 0; q < 4; q++)
            acc2[q] = add2(acc2[q], __shfl_xor_sync(0xffffffffu, acc2[q], 16));
#pragma unroll
        for (int q = 0; q < 4; q++)
            acc2[q] = add2(acc2[q], __shfl_xor_sync(0xffffffffu, acc2[q], 8));
        u64t v = (g == 0) ? acc2[0] : (g == 1) ? acc2[1] : (g == 2) ? acc2[2] : acc2[3];
        v = add2(v, __shfl_xor_sync(0xffffffffu, v, 4));
        v = add2(v, __shfl_xor_sync(0xffffffffu, v, 2));
        v = add2(v, __shfl_xor_sync(0xffffffffu, v, 1));
        if ((lane & 7) == (n & 7)) {
            float x, y; unpack2(v, x, y);
            *(float2*)(outg + n * 8 + 2 * g) = make_float2(x + boP.x, y + boP.y);
        }
    }
}

__global__ void __launch_bounds__(NT, 2)
main_kernel(const float* __restrict__ x, const float* __restrict__ U,
            const float* __restrict__ Wp, const float* __restrict__ bp,
            const float* __restrict__ g1, const float* __restrict__ be1,
            const float* __restrict__ g3, const float* __restrict__ be3,
            const float* __restrict__ Wo, const float* __restrict__ bo,
            float* __restrict__ out)
{
    extern __shared__ float sm[];
    float* sFX  = sm + O_FX;
    float* sUmD = sm + O_UMD;
    float* sUm  = sm + O_UM;
    float* sWp  = sm + O_WP;
    float* sV   = sm + O_V;
    float* sY   = sm + O_Y;
    u64t*  sWoB = (u64t*)(sm + O_WOB);

    const int tid = threadIdx.x;
    const int wid = tid >> 5, lane = tid & 31;

    // ---- init: weights/vectors ----
    if (tid < 64) {
#pragma unroll
        for (int k = 0; k < 8; k++) {
            float v = U[tid * 64 + k];
            sUm[tid * 8 + k] = v;
            sUmD[tid * 16 + 2 * k]     = v;
            sUmD[tid * 16 + 2 * k + 1] = v;
        }
    }
    for (int i = tid; i < 1024; i += NT) sWp[i] = Wp[i];
    if (tid < 128) {
        sV[tid]       = bp[tid];
        sV[128 + tid] = d_b1[tid];
        sV[256 + tid] = d_b3[tid];
        sV[384 + tid] = g1[tid];
        sV[512 + tid] = be1[tid];
        sV[640 + tid] = g3[tid];
        sV[768 + tid] = be3[tid];
    }
    if (tid < 8) { sV[896 + tid] = bo[tid]; sV[904 + tid] = d_tv[tid]; }
    if (tid < 256) {
        const int l = tid >> 3, u = (tid & 7) ^ (l & 7);
        const int j = u >> 1, qb = (u & 1) * 2;
        const int c = 4 * l + j;
        sWoB[2 * tid]     = pack2(Wo[c * 8 + 2 * qb],     Wo[c * 8 + 2 * qb + 1]);
        sWoB[2 * tid + 1] = pack2(Wo[c * 8 + 2 * qb + 2], Wo[c * 8 + 2 * qb + 3]);
    }
    __syncthreads();

    // ---- stage A pass 1: y[t][k][p] = sum_n Um[n,k] x[t][n][p] ----
    {
        const int k = lane >> 2, q = lane & 3;
        const float2* xg2 = (const float2*)(x + (size_t)blockIdx.x * 4096 + wid * 512);
        u64t acc = 0ull;
#pragma unroll 4
        for (int n = 0; n < 64; n++) {
            u64t umP = *(const u64t*)(sUmD + n * 16 + 2 * k);  // dup pair
            float2 xv = __ldg(&xg2[n * 4 + q]);
            fma2(acc, umP, pack2(xv.x, xv.y));
        }
        float a, b; unpack2(acc, a, b);
        *(float2*)(sY + wid * 64 + k * 8 + 2 * q) = make_float2(a, b);
    }
    __syncthreads();

    // ---- stage A pass 2: XF[t][k][c] = tv[k]*bp[c] + sum_p y[t][k][p] Wp[p][c] ----
    // warp k writes rows (t,k) -> consumed by the same warp in mode_gemm (no sync)
    {
        const int k = wid, c4 = lane;
        const float tvk = sV[904 + k];
        const float4 bp4 = ((const float4*)sV)[c4];
#pragma unroll
        for (int t = 0; t < TT; t++) {
            const float* yv = sY + t * 64 + k * 8;
            u64t a01 = 0ull, a23 = 0ull;
            u64t tb = dup2(tvk);
            fma2(a01, tb, pack2(bp4.x, bp4.y));
            fma2(a23, tb, pack2(bp4.z, bp4.w));
#pragma unroll
            for (int p = 0; p < 8; p++) {
                u64t yb = dup2(yv[p]);
                float4 wp = ((const float4*)(sWp + p * 128))[c4];
                fma2(a01, yb, pack2(wp.x, wp.y));
                fma2(a23, yb, pack2(wp.z, wp.w));
            }
            float a, b, c, d;
            unpack2(a01, a, b); unpack2(a23, c, d);
            *(float4*)(sFX + (t * 8 + k) * 128 + 4 * c4) = make_float4(a, b, c, d);
        }
    }

    // ---- stage B: f0 = per-mode GEMM with M0 (in place) ----
    mode_gemm(d_M0, sFX, tid);
    __syncthreads();

    // ---- stage C: warp w handles tile w entirely ----
    tile_stageC(sFX, sUmD, sV, wid, lane);
    __syncthreads();

    // ---- stage D: f2 = per-mode GEMM with M2 (in place) ----
    mode_gemm(d_M2, sFX, tid);
    __syncthreads();

    // ---- stage E: warp w handles tile w entirely, fused output projection ----
    float* outg = out + (size_t)blockIdx.x * 4096;
    tile_stageE(sFX, sUmD, sV, sWoB, outg + wid * 512, wid, lane);
}

// ------------------------------- launch ------------------------------------

extern "C" void kernel_launch(void* const* d_in, const int* in_sizes, int n_in,
                              void* d_out, int out_size)
{
    const float* x   = (const float*)d_in[0];
    const float* adj = (const float*)d_in[1];
    const float* U   = (const float*)d_in[2];
    const float* Wp  = (const float*)d_in[3];
    const float* bp  = (const float*)d_in[4];
    const float* w0  = (const float*)d_in[5];
    const float* w2  = (const float*)d_in[6];
    const float* Ws1 = (const float*)d_in[7];
    const float* bs1 = (const float*)d_in[8];
    const float* Wn1 = (const float*)d_in[9];
    const float* bn1 = (const float*)d_in[10];
    const float* g1  = (const float*)d_in[11];
    const float* be1 = (const float*)d_in[12];
    const float* Ws3 = (const float*)d_in[13];
    const float* bs3 = (const float*)d_in[14];
    const float* Wn3 = (const float*)d_in[15];
    const float* bn3 = (const float*)d_in[16];
    const float* g3  = (const float*)d_in[17];
    const float* be3 = (const float*)d_in[18];
    const float* Wo  = (const float*)d_in[19];
    const float* bo  = (const float*)d_in[20];
    float* out = (float*)d_out;

    pre_kernel<<<256, 128>>>(U, adj, w0, w2, Ws1, Wn1, Ws3, Wn3,
                             bs1, bn1, bs3, bn3);

    const size_t smem = SMEMF * sizeof(float);  // 52 KB -> 2 CTAs/SM
    cudaFuncSetAttribute(main_kernel, cudaFuncAttributeMaxDynamicSharedMemorySize,
                         (int)smem);
    main_kernel<<<2048, NT, smem>>>(x, U, Wp, bp, g1, be1, g3, be3, Wo, bo, out);
}

// round 10
// speedup vs baseline: 1.0568x; 1.0568x over previous
#include <cuda_runtime.h>

// ---------------------------------------------------------------------------
// Model_19095424598065 v10 : algebraically reduced graph-spectral net.
// = v4 main kernel (best measured) with ONE change: mode_gemm uses K-paired
// f32x2 accumulation with a COALESCED lane->column mapping (lane l owns cols
// {2l,2l+1,64+2l,64+2l+1}), so M streams as coalesced LDG.128 of pre-paired
// operands and the x operand is a raw u64 from the scalar XF layout —
// zero operand-marshalling MOVs in the hot loop. Fused single pre_kernel.
// ---------------------------------------------------------------------------

typedef unsigned long long u64t;

#define NT 256
#define TT 8

// M stored K-pair-transposed: d_M[k][ip][2c+e] = M_k[2*ip+e][c]
__device__ float d_M0[8 * 128 * 128];
__device__ float d_M2[8 * 128 * 128];
__device__ float d_tv[8];
__device__ float d_b1[128];
__device__ float d_b3[128];

// ------------------------------ helpers ------------------------------------
static __device__ __forceinline__ u64t dup2(float x) {
    u64t r; asm("mov.b64 %0, {%1, %1};" : "=l"(r) : "f"(x)); return r;
}
static __device__ __forceinline__ u64t pack2(float a, float b) {
    u64t r; asm("mov.b64 %0, {%1, %2};" : "=l"(r) : "f"(a), "f"(b)); return r;
}
static __device__ __forceinline__ void unpack2(u64t v, float& a, float& b) {
    asm("mov.b64 {%0, %1}, %2;" : "=f"(a), "=f"(b) : "l"(v));
}
static __device__ __forceinline__ void fma2(u64t& d, u64t a, u64t b) {
    asm("fma.rn.f32x2 %0, %1, %2, %3;" : "=l"(d) : "l"(a), "l"(b), "l"(d));
}
static __device__ __forceinline__ u64t add2(u64t a, u64t b) {
    u64t r; asm("add.rn.f32x2 %0, %1, %2;" : "=l"(r) : "l"(a), "l"(b)); return r;
}
static __device__ __forceinline__ float fold2(u64t v) {
    float a, b; unpack2(v, a, b); return a + b;
}

// --------------------------- fused precompute ------------------------------
// 256 blocks: b<128 -> M0 row b; b>=128 -> M2 row b-128. lam computed locally.
__global__ void pre_kernel(const float* __restrict__ U, const float* __restrict__ adj,
                           const float* __restrict__ w0, const float* __restrict__ w2,
                           const float* __restrict__ Ws1, const float* __restrict__ Wn1,
                           const float* __restrict__ Ws3, const float* __restrict__ Wn3,
                           const float* __restrict__ bs1, const float* __restrict__ bn1,
                           const float* __restrict__ bs3, const float* __restrict__ bn3)
{
    __shared__ float sw[1024];
    __shared__ float spart[128];
    __shared__ float slam[8];
    const int b = blockIdx.x, c = threadIdx.x;
    const int which = b >> 7, i = b & 127;
    const float* w  = which ? w2  : w0;
    const float* Ws = which ? Ws3 : Ws1;
    const float* Wn = which ? Wn3 : Wn1;

    {
        const int k = c >> 4, s = c & 15;
        float part = 0.f;
        for (int n = s; n < 64; n += 16) {
            float g = 0.f;
            for (int m = 0; m < 64; m++) g += adj[n * 64 + m] * U[m * 64 + k];
            part += U[n * 64 + k] * g;
        }
        spart[c] = part;
    }
    for (int idx = c; idx < 1024; idx += 128) sw[idx] = w[i * 1024 + idx];
    __syncthreads();
    if (c < 8) {
        float lam = 0.f;
        for (int s = 0; s < 16; s++) lam += spart[c * 16 + s];
        slam[c] = lam;
    }
    if (b == 0) {
        if (c < 128) { d_b1[c] = bs1[c] + bn1[c]; d_b3[c] = bs3[c] + bn3[c]; }
        if (c < 8) {
            float ts = 0.f;
            for (int n = 0; n < 64; n++) ts += U[n * 64 + c];
            d_tv[c] = ts;
        }
    }
    __syncthreads();

    float lam[8], acc[8];
#pragma unroll
    for (int k = 0; k < 8; k++) { lam[k] = slam[k]; acc[k] = 0.f; }
#pragma unroll 2
    for (int j = 0; j < 128; j++) {
        float ws = __ldg(Ws + j * 128 + c);
        float wn = __ldg(Wn + j * 128 + c);
#pragma unroll
        for (int k = 0; k < 8; k++)
            acc[k] += sw[j * 8 + k] * fmaf(lam[k], wn, ws);
    }
    // K-pair-transposed store: [k][i>>1][2c + (i&1)]
    float* M = which ? d_M2 : d_M0;
    const int off = (i >> 1) * 256 + 2 * c + (i & 1);
#pragma unroll
    for (int k = 0; k < 8; k++) M[k * 16384 + off] = acc[k];
}

// ------------------------------- main kernel -------------------------------
// smem (floats):
//  sFX  [0    , 8192 )  XF/F in place [t][k][c]
//  sUm  [8192 , 8704 )  Um[n][k] stride 8
//  sWp  [8704 , 9728 )  Wp[p][c]
//  sV   [9728 , 10752)  bp|b1|b3|g1|be1|g3|be3|bo(8)|tv(8)
//  sY   [10752, 11264)  stage-A y[t][k][p]
//  sWoB [11264, 12288)  Wo pairs, per-lane swizzled (512 u64)
#define O_FX  0
#define O_UM  8192
#define O_WP  8704
#define O_V   9728
#define O_Y   10752
#define O_WOB 11264
#define SMEMF 12288

// F[t,k,:] = XF[t,k,:] @ M_k (K=128), in place. Warp k owns mode k's rows.
// f32x2 lanes paired over K (even/odd partial sums). Lane l owns columns
// {2l, 2l+1, 64+2l, 64+2l+1}: every M load is a coalesced LDG.128 of two
// pre-paired column operands; x operand is a raw u64 from scalar XF.
static __device__ __forceinline__ void mode_gemm(const float* __restrict__ M,
                                                 float* sFX, int tid)
{
    const int k = tid >> 5, lane = tid & 31;
    const ulonglong2* Mu = (const ulonglong2*)(M + k * 16384);  // 64 u2 per ip-row
    u64t acc[TT][4];
#pragma unroll
    for (int t = 0; t < TT; t++)
#pragma unroll
        for (int q = 0; q < 4; q++) acc[t][q] = 0ull;

#pragma unroll 2
    for (int i4 = 0; i4 < 32; i4++) {
        // ip0 = 2*i4 (K 4i4,4i4+1), ip1 = 2*i4+1 (K 4i4+2,4i4+3)
        ulonglong2 A0 = __ldg(&Mu[(2 * i4)     * 64 + lane]);       // ip0 cols 2l,2l+1
        ulonglong2 A1 = __ldg(&Mu[(2 * i4)     * 64 + 32 + lane]);  // ip0 cols 64+2l,65+2l
        ulonglong2 B0 = __ldg(&Mu[(2 * i4 + 1) * 64 + lane]);       // ip1 cols 2l,2l+1
        ulonglong2 B1 = __ldg(&Mu[(2 * i4 + 1) * 64 + 32 + lane]);  // ip1 cols 64+2l,65+2l
#pragma unroll
        for (int t = 0; t < TT; t++) {
            // (x_{4i4},x_{4i4+1}),(x_{4i4+2},x_{4i4+3}) — uniform broadcast
            ulonglong2 xq = *(const ulonglong2*)(sFX + (t * 8 + k) * 128 + 4 * i4);
            fma2(acc[t][0], xq.x, A0.x); fma2(acc[t][1], xq.x, A0.y);
            fma2(acc[t][2], xq.x, A1.x); fma2(acc[t][3], xq.x, A1.y);
            fma2(acc[t][0], xq.y, B0.x); fma2(acc[t][1], xq.y, B0.y);
            fma2(acc[t][2], xq.y, B1.x); fma2(acc[t][3], xq.y, B1.y);
        }
    }
#pragma unroll
    for (int t = 0; t < TT; t++) {
        float* row = sFX + (t * 8 + k) * 128;
        *(float2*)(row + 2 * lane)      = make_float2(fold2(acc[t][0]), fold2(acc[t][1]));
        *(float2*)(row + 64 + 2 * lane) = make_float2(fold2(acc[t][2]), fold2(acc[t][3]));
    }
}

// Stage C, one warp = one tile t (v4 verbatim).
static __device__ __forceinline__ void tile_stageC(float* sFX, const float* sUm,
                                                   const float* sV, int t, int lane)
{
    u64t Fr0[8], Fr1[8];
#pragma unroll
    for (int k = 0; k < 8; k++) {
        float4 f = *(const float4*)(sFX + (t * 8 + k) * 128 + 4 * lane);
        Fr0[k] = pack2(f.x, f.y); Fr1[k] = pack2(f.z, f.w);
    }
    const float4 bq = *(const float4*)(sV + 128 + 4 * lane);
    const float4 gq = *(const float4*)(sV + 384 + 4 * lane);
    const float4 eq = *(const float4*)(sV + 512 + 4 * lane);
    const u64t b01 = pack2(bq.x, bq.y), b23 = pack2(bq.z, bq.w);

    u64t X20[8], X21[8];
#pragma unroll
    for (int k = 0; k < 8; k++) { X20[k] = 0ull; X21[k] = 0ull; }

#pragma unroll 4
    for (int n = 0; n < 64; n++) {
        float4 u0 = *(const float4*)(sUm + n * 8);      // uniform -> broadcast
        float4 u1 = *(const float4*)(sUm + n * 8 + 4);
        u64t uk[8] = {dup2(u0.x), dup2(u0.y), dup2(u0.z), dup2(u0.w),
                      dup2(u1.x), dup2(u1.y), dup2(u1.z), dup2(u1.w)};
        u64t o0 = b01, o1 = b23;
#pragma unroll
        for (int k = 0; k < 8; k++) { fma2(o0, uk[k], Fr0[k]); fma2(o1, uk[k], Fr1[k]); }
        float a, b, c, d;
        unpack2(o0, a, b); unpack2(o1, c, d);
        float s = a + b + c + d;
        float s2 = a * a + b * b + c * c + d * d;
#pragma unroll
        for (int m = 1; m < 32; m <<= 1) {
            s  += __shfl_xor_sync(0xffffffffu, s, m);
            s2 += __shfl_xor_sync(0xffffffffu, s2, m);
        }
        const float mu = s * 0.0078125f;
        const float rstd = rsqrtf(s2 * 0.0078125f - mu * mu + 1e-5f);
        u64t hA = pack2(fmaxf((a - mu) * rstd * gq.x + eq.x, 0.f),
                        fmaxf((b - mu) * rstd * gq.y + eq.y, 0.f));
        u64t hB = pack2(fmaxf((c - mu) * rstd * gq.z + eq.z, 0.f),
                        fmaxf((d - mu) * rstd * gq.w + eq.w, 0.f));
#pragma unroll
        for (int k = 0; k < 8; k++) { fma2(X20[k], uk[k], hA); fma2(X21[k], uk[k], hB); }
    }
#pragma unroll
    for (int k = 0; k < 8; k++) {
        float a, b, c, d;
        unpack2(X20[k], a, b); unpack2(X21[k], c, d);
        *(float4*)(sFX + (t * 8 + k) * 128 + 4 * lane) = make_float4(a, b, c, d);
    }
}

// Stage E, one warp = one tile (v4 verbatim).
static __device__ __forceinline__ void tile_stageE(const float* sFX, const float* sUm,
                                                   const float* sV, const u64t* sWoB,
                                                   float* __restrict__ outg,
                                                   int t, int lane)
{
    u64t Fr0[8], Fr1[8];
#pragma unroll
    for (int k = 0; k < 8; k++) {
        float4 f = *(const float4*)(sFX + (t * 8 + k) * 128 + 4 * lane);
        Fr0[k] = pack2(f.x, f.y); Fr1[k] = pack2(f.z, f.w);
    }
    const float4 bq = *(const float4*)(sV + 256 + 4 * lane);
    const float4 gq = *(const float4*)(sV + 640 + 4 * lane);
    const float4 eq = *(const float4*)(sV + 768 + 4 * lane);
    const u64t b01 = pack2(bq.x, bq.y), b23 = pack2(bq.z, bq.w);

    u64t w2[4][4];
    {
        const int l7 = lane & 7;
#pragma unroll
        for (int u = 0; u < 8; u++) {
            int p = lane * 8 + (u ^ l7);
            u64t A = sWoB[2 * p], B = sWoB[2 * p + 1];
            const int j = u >> 1, qb = (u & 1) * 2;
            w2[j][qb] = A; w2[j][qb + 1] = B;
        }
    }
    const int g = lane >> 3;
    float2 boP = *(const float2*)(sV + 896 + 2 * g);

#pragma unroll 2
    for (int n = 0; n < 64; n++) {
        float4 u0 = *(const float4*)(sUm + n * 8);
        float4 u1 = *(const float4*)(sUm + n * 8 + 4);
        u64t uk[8] = {dup2(u0.x), dup2(u0.y), dup2(u0.z), dup2(u0.w),
                      dup2(u1.x), dup2(u1.y), dup2(u1.z), dup2(u1.w)};
        u64t o0 = b01, o1 = b23;
#pragma unroll
        for (int k = 0; k < 8; k++) { fma2(o0, uk[k], Fr0[k]); fma2(o1, uk[k], Fr1[k]); }
        float a, b, c, d;
        unpack2(o0, a, b); unpack2(o1, c, d);
        float s = a + b + c + d;
        float s2 = a * a + b * b + c * c + d * d;
#pragma unroll
        for (int m = 1; m < 32; m <<= 1) {
            s  += __shfl_xor_sync(0xffffffffu, s, m);
            s2 += __shfl_xor_sync(0xffffffffu, s2, m);
        }
        const float mu = s * 0.0078125f;
        const float rstd = rsqrtf(s2 * 0.0078125f - mu * mu + 1e-5f);
        float h0 = fmaxf((a - mu) * rstd * gq.x + eq.x, 0.f);
        float h1 = fmaxf((b - mu) * rstd * gq.y + eq.y, 0.f);
        float h2 = fmaxf((c - mu) * rstd * gq.z + eq.z, 0.f);
        float h3 = fmaxf((d - mu) * rstd * gq.w + eq.w, 0.f);

        u64t acc2[4] = {0ull, 0ull, 0ull, 0ull};
        u64t hb;
        hb = dup2(h0);
#pragma unroll
        for (int q = 0; q < 4; q++) fma2(acc2[q], hb, w2[0][q]);
        hb = dup2(h1);
#pragma unroll
        for (int q = 0; q < 4; q++) fma2(acc2[q], hb, w2[1][q]);
        hb = dup2(h2);
#pragma unroll
        for (int q = 0; q < 4; q++) fma2(acc2[q], hb, w2[2][q]);
        hb = dup2(h3);
#pragma unroll
        for (int q = 0; q < 4; q++) fma2(acc2[q], hb, w2[3][q]);

#pragma unroll
        for (int q = 0; q < 4; q++)
            acc2[q] = add2(acc2[q], __shfl_xor_sync(0xffffffffu, acc2[q], 16));
#pragma unroll
        for (int q = 0; q < 4; q++)
            acc2[q] = add2(acc2[q], __shfl_xor_sync(0xffffffffu, acc2[q], 8));
        u64t v = (g == 0) ? acc2[0] : (g == 1) ? acc2[1] : (g == 2) ? acc2[2] : acc2[3];
        v = add2(v, __shfl_xor_sync(0xffffffffu, v, 4));
        v = add2(v, __shfl_xor_sync(0xffffffffu, v, 2));
        v = add2(v, __shfl_xor_sync(0xffffffffu, v, 1));
        if ((lane & 7) == (n & 7)) {
            float x, y; unpack2(v, x, y);
            *(float2*)(outg + n * 8 + 2 * g) = make_float2(x + boP.x, y + boP.y);
        }
    }
}

__global__ void __launch_bounds__(NT, 2)
main_kernel(const float* __restrict__ x, const float* __restrict__ U,
            const float* __restrict__ Wp, const float* __restrict__ bp,
            const float* __restrict__ g1, const float* __restrict__ be1,
            const float* __restrict__ g3, const float* __restrict__ be3,
            const float* __restrict__ Wo, const float* __restrict__ bo,
            float* __restrict__ out)
{
    extern __shared__ float sm[];
    float* sFX  = sm + O_FX;
    float* sUm  = sm + O_UM;
    float* sWp  = sm + O_WP;
    float* sV   = sm + O_V;
    float* sY   = sm + O_Y;
    u64t*  sWoB = (u64t*)(sm + O_WOB);

    const int tid = threadIdx.x;
    const int wid = tid >> 5, lane = tid & 31;

    // ---- init: weights/vectors ----
    if (tid < 64) {
#pragma unroll
        for (int k = 0; k < 8; k++) sUm[tid * 8 + k] = U[tid * 64 + k];
    }
    for (int i = tid; i < 1024; i += NT) sWp[i] = Wp[i];
    if (tid < 128) {
        sV[tid]       = bp[tid];
        sV[128 + tid] = d_b1[tid];
        sV[256 + tid] = d_b3[tid];
        sV[384 + tid] = g1[tid];
        sV[512 + tid] = be1[tid];
        sV[640 + tid] = g3[tid];
        sV[768 + tid] = be3[tid];
    }
    if (tid < 8) { sV[896 + tid] = bo[tid]; sV[904 + tid] = d_tv[tid]; }
    if (tid < 256) {
        const int l = tid >> 3, u = (tid & 7) ^ (l & 7);
        const int j = u >> 1, qb = (u & 1) * 2;
        const int c = 4 * l + j;
        sWoB[2 * tid]     = pack2(Wo[c * 8 + 2 * qb],     Wo[c * 8 + 2 * qb + 1]);
        sWoB[2 * tid + 1] = pack2(Wo[c * 8 + 2 * qb + 2], Wo[c * 8 + 2 * qb + 3]);
    }
    __syncthreads();

    // ---- stage A pass 1: y[t][k][p] = sum_n Um[n,k] x[t][n][p] ----
    {
        const int k = lane >> 2, q = lane & 3;
        const float2* xg2 = (const float2*)(x + (size_t)blockIdx.x * 4096 + wid * 512);
        u64t acc = 0ull;
#pragma unroll 4
        for (int n = 0; n < 64; n++) {
            float um = sUm[n * 8 + k];
            float2 xv = __ldg(&xg2[n * 4 + q]);
            fma2(acc, dup2(um), pack2(xv.x, xv.y));
        }
        float a, b; unpack2(acc, a, b);
        *(float2*)(sY + wid * 64 + k * 8 + 2 * q) = make_float2(a, b);
    }
    __syncthreads();

    // ---- stage A pass 2: XF[t][k][c] = tv[k]*bp[c] + sum_p y[t][k][p] Wp[p][c] ----
    // warp k writes rows (t,k) -> consumed by the same warp in mode_gemm (no sync)
    {
        const int k = wid, c4 = lane;
        const float tvk = sV[904 + k];
        const float4 bp4 = ((const float4*)sV)[c4];
#pragma unroll
        for (int t = 0; t < TT; t++) {
            const float* yv = sY + t * 64 + k * 8;
            u64t a01 = 0ull, a23 = 0ull;
            u64t tb = dup2(tvk);
            fma2(a01, tb, pack2(bp4.x, bp4.y));
            fma2(a23, tb, pack2(bp4.z, bp4.w));
#pragma unroll
            for (int p = 0; p < 8; p++) {
                u64t yb = dup2(yv[p]);
                float4 wp = ((const float4*)(sWp + p * 128))[c4];
                fma2(a01, yb, pack2(wp.x, wp.y));
                fma2(a23, yb, pack2(wp.z, wp.w));
            }
            float a, b, c, d;
            unpack2(a01, a, b); unpack2(a23, c, d);
            *(float4*)(sFX + (t * 8 + k) * 128 + 4 * c4) = make_float4(a, b, c, d);
        }
    }

    // ---- stage B: f0 = per-mode GEMM with M0 (in place) ----
    mode_gemm(d_M0, sFX, tid);
    __syncthreads();

    // ---- stage C: warp w handles tile w entirely ----
    tile_stageC(sFX, sUm, sV, wid, lane);
    __syncthreads();

    // ---- stage D: f2 = per-mode GEMM with M2 (in place) ----
    mode_gemm(d_M2, sFX, tid);
    __syncthreads();

    // ---- stage E: warp w handles tile w entirely, fused output projection ----
    float* outg = out + (size_t)blockIdx.x * 4096;
    tile_stageE(sFX, sUm, sV, sWoB, outg + wid * 512, wid, lane);
}

// ------------------------------- launch ------------------------------------

extern "C" void kernel_launch(void* const* d_in, const int* in_sizes, int n_in,
                              void* d_out, int out_size)
{
    const float* x   = (const float*)d_in[0];
    const float* adj = (const float*)d_in[1];
    const float* U   = (const float*)d_in[2];
    const float* Wp  = (const float*)d_in[3];
    const float* bp  = (const float*)d_in[4];
    const float* w0  = (const float*)d_in[5];
    const float* w2  = (const float*)d_in[6];
    const float* Ws1 = (const float*)d_in[7];
    const float* bs1 = (const float*)d_in[8];
    const float* Wn1 = (const float*)d_in[9];
    const float* bn1 = (const float*)d_in[10];
    const float* g1  = (const float*)d_in[11];
    const float* be1 = (const float*)d_in[12];
    const float* Ws3 = (const float*)d_in[13];
    const float* bs3 = (const float*)d_in[14];
    const float* Wn3 = (const float*)d_in[15];
    const float* bn3 = (const float*)d_in[16];
    const float* g3  = (const float*)d_in[17];
    const float* be3 = (const float*)d_in[18];
    const float* Wo  = (const float*)d_in[19];
    const float* bo  = (const float*)d_in[20];
    float* out = (float*)d_out;

    pre_kernel<<<256, 128>>>(U, adj, w0, w2, Ws1, Wn1, Ws3, Wn3,
                             bs1, bn1, bs3, bn3);

    const size_t smem = SMEMF * sizeof(float);  // 48 KB -> 2 CTAs/SM
    cudaFuncSetAttribute(main_kernel, cudaFuncAttributeMaxDynamicSharedMemorySize,
                         (int)smem);
    main_kernel<<<2048, NT, smem>>>(x, U, Wp, bp, g1, be1, g3, be3, Wo, bo, out);
}

// round 11
// speedup vs baseline: 1.0662x; 1.0089x over previous
#include <cuda_runtime.h>

// ---------------------------------------------------------------------------
// Model_19095424598065 v11 : algebraically reduced graph-spectral net.
// = v4 main kernel EXACTLY (best measured mode_gemm + stages, 544us kernel)
//   + fused single pre_kernel (proven -90us bench overhead)
//   + ONE isolated change: Um read as dup-pairs from smem in stages C/E
//     (2 uniform LDS.128/node instead of 2 LDS.128 + 16 MOVs/node).
// ---------------------------------------------------------------------------

typedef unsigned long long u64t;

#define NT 256
#define TT 8

__device__ float d_M0[8 * 128 * 128];   // scalar layout [k][i][c] (v4)
__device__ float d_M2[8 * 128 * 128];
__device__ float d_tv[8];
__device__ float d_b1[128];
__device__ float d_b3[128];

// ------------------------------ helpers ------------------------------------
static __device__ __forceinline__ u64t dup2(float x) {
    u64t r; asm("mov.b64 %0, {%1, %1};" : "=l"(r) : "f"(x)); return r;
}
static __device__ __forceinline__ u64t pack2(float a, float b) {
    u64t r; asm("mov.b64 %0, {%1, %2};" : "=l"(r) : "f"(a), "f"(b)); return r;
}
static __device__ __forceinline__ void unpack2(u64t v, float& a, float& b) {
    asm("mov.b64 {%0, %1}, %2;" : "=f"(a), "=f"(b) : "l"(v));
}
static __device__ __forceinline__ void fma2(u64t& d, u64t a, u64t b) {
    asm("fma.rn.f32x2 %0, %1, %2, %3;" : "=l"(d) : "l"(a), "l"(b), "l"(d));
}
static __device__ __forceinline__ u64t add2(u64t a, u64t b) {
    u64t r; asm("add.rn.f32x2 %0, %1, %2;" : "=l"(r) : "l"(a), "l"(b)); return r;
}

// --------------------------- fused precompute ------------------------------
// 256 blocks: b<128 -> M0 row b; b>=128 -> M2 row b-128. lam computed locally.
// Scalar M layout (v4): M[(k*128 + i)*128 + c].
__global__ void pre_kernel(const float* __restrict__ U, const float* __restrict__ adj,
                           const float* __restrict__ w0, const float* __restrict__ w2,
                           const float* __restrict__ Ws1, const float* __restrict__ Wn1,
                           const float* __restrict__ Ws3, const float* __restrict__ Wn3,
                           const float* __restrict__ bs1, const float* __restrict__ bn1,
                           const float* __restrict__ bs3, const float* __restrict__ bn3)
{
    __shared__ float sw[1024];
    __shared__ float spart[128];
    __shared__ float slam[8];
    const int b = blockIdx.x, c = threadIdx.x;
    const int which = b >> 7, i = b & 127;
    const float* w  = which ? w2  : w0;
    const float* Ws = which ? Ws3 : Ws1;
    const float* Wn = which ? Wn3 : Wn1;

    {
        const int k = c >> 4, s = c & 15;
        float part = 0.f;
        for (int n = s; n < 64; n += 16) {
            float g = 0.f;
            for (int m = 0; m < 64; m++) g += adj[n * 64 + m] * U[m * 64 + k];
            part += U[n * 64 + k] * g;
        }
        spart[c] = part;
    }
    for (int idx = c; idx < 1024; idx += 128) sw[idx] = w[i * 1024 + idx];
    __syncthreads();
    if (c < 8) {
        float lam = 0.f;
        for (int s = 0; s < 16; s++) lam += spart[c * 16 + s];
        slam[c] = lam;
    }
    if (b == 0) {
        if (c < 128) { d_b1[c] = bs1[c] + bn1[c]; d_b3[c] = bs3[c] + bn3[c]; }
        if (c < 8) {
            float ts = 0.f;
            for (int n = 0; n < 64; n++) ts += U[n * 64 + c];
            d_tv[c] = ts;
        }
    }
    __syncthreads();

    float lam[8], acc[8];
#pragma unroll
    for (int k = 0; k < 8; k++) { lam[k] = slam[k]; acc[k] = 0.f; }
#pragma unroll 2
    for (int j = 0; j < 128; j++) {
        float ws = __ldg(Ws + j * 128 + c);
        float wn = __ldg(Wn + j * 128 + c);
#pragma unroll
        for (int k = 0; k < 8; k++)
            acc[k] += sw[j * 8 + k] * fmaf(lam[k], wn, ws);
    }
    float* M = which ? d_M2 : d_M0;
#pragma unroll
    for (int k = 0; k < 8; k++) M[(k * 128 + i) * 128 + c] = acc[k];
}

// ------------------------------- main kernel -------------------------------
// smem (floats):
//  sFX  [0    , 8192 )  XF/F in place [t][k][c]
//  sUm  [8192 , 8704 )  Um[n][k] stride 8 (stage A)
//  sUmD [8704 , 9728 )  Um dup pairs: row n = 16 floats (u_k,u_k)x8 (stages C/E)
//  sWp  [9728 , 10752)  Wp[p][c]
//  sV   [10752, 11776)  bp|b1|b3|g1|be1|g3|be3|bo(8)|tv(8)
//  sY   [11776, 12288)  stage-A y[t][k][p]
//  sWoB [12288, 13312)  Wo pairs, per-lane swizzled (512 u64)
#define O_FX  0
#define O_UM  8192
#define O_UMD 8704
#define O_WP  9728
#define O_V   10752
#define O_Y   11776
#define O_WOB 12288
#define SMEMF 13312

// F[t,k,:] = XF[t,k,:] @ M_k (K=128), in place. Warp k owns mode k's rows.
// v4 verbatim — the best-measured formulation (ptxas unroll-2 pipelines it).
static __device__ __forceinline__ void mode_gemm(const float* __restrict__ M,
                                                 float* sFX, int tid)
{
    const int k = tid >> 5, lane = tid & 31;
    const float4* Mk4 = (const float4*)(M + k * 16384);
    u64t a01[TT], a23[TT];
#pragma unroll
    for (int t = 0; t < TT; t++) { a01[t] = 0ull; a23[t] = 0ull; }

#pragma unroll 2
    for (int i4 = 0; i4 < 32; i4++) {
        float4 xv[TT];
#pragma unroll
        for (int t = 0; t < TT; t++)  // uniform address -> broadcast, 1 wf
            xv[t] = *(const float4*)(sFX + (t * 8 + k) * 128 + 4 * i4);
#pragma unroll
        for (int ii = 0; ii < 4; ii++) {
            float4 m = __ldg(&Mk4[(4 * i4 + ii) * 32 + lane]);
            u64t m01 = pack2(m.x, m.y), m23 = pack2(m.z, m.w);
#pragma unroll
            for (int t = 0; t < TT; t++) {
                float xs = (ii == 0) ? xv[t].x : (ii == 1) ? xv[t].y
                         : (ii == 2) ? xv[t].z : xv[t].w;
                u64t xb = dup2(xs);
                fma2(a01[t], xb, m01);
                fma2(a23[t], xb, m23);
            }
        }
    }
#pragma unroll
    for (int t = 0; t < TT; t++) {
        float a, b, c, d;
        unpack2(a01[t], a, b); unpack2(a23[t], c, d);
        *(float4*)(sFX + (t * 8 + k) * 128 + 4 * lane) = make_float4(a, b, c, d);
    }
}

// Stage C, one warp = one tile t: o = Um@F + b1 -> LN -> relu -> xf2 = Um^T h.
// v4 except Um read as dup pairs (2 uniform LDS.128/node, zero MOVs).
static __device__ __forceinline__ void tile_stageC(float* sFX, const float* sUmD,
                                                   const float* sV, int t, int lane)
{
    u64t Fr0[8], Fr1[8];
#pragma unroll
    for (int k = 0; k < 8; k++) {
        float4 f = *(const float4*)(sFX + (t * 8 + k) * 128 + 4 * lane);
        Fr0[k] = pack2(f.x, f.y); Fr1[k] = pack2(f.z, f.w);
    }
    const float4 bq = *(const float4*)(sV + 128 + 4 * lane);
    const float4 gq = *(const float4*)(sV + 384 + 4 * lane);
    const float4 eq = *(const float4*)(sV + 512 + 4 * lane);
    const u64t b01 = pack2(bq.x, bq.y), b23 = pack2(bq.z, bq.w);

    u64t X20[8], X21[8];
#pragma unroll
    for (int k = 0; k < 8; k++) { X20[k] = 0ull; X21[k] = 0ull; }

#pragma unroll 4
    for (int n = 0; n < 64; n++) {
        ulonglong2 uA = *(const ulonglong2*)(sUmD + n * 16);       // (u0,u0),(u1,u1)
        ulonglong2 uB = *(const ulonglong2*)(sUmD + n * 16 + 4);   // u2,u3
        ulonglong2 uC = *(const ulonglong2*)(sUmD + n * 16 + 8);   // u4,u5
        ulonglong2 uD = *(const ulonglong2*)(sUmD + n * 16 + 12);  // u6,u7
        u64t uk[8] = {uA.x, uA.y, uB.x, uB.y, uC.x, uC.y, uD.x, uD.y};
        u64t o0 = b01, o1 = b23;
#pragma unroll
        for (int k = 0; k < 8; k++) { fma2(o0, uk[k], Fr0[k]); fma2(o1, uk[k], Fr1[k]); }
        float a, b, c, d;
        unpack2(o0, a, b); unpack2(o1, c, d);
        float s = a + b + c + d;
        float s2 = a * a + b * b + c * c + d * d;
#pragma unroll
        for (int m = 1; m < 32; m <<= 1) {
            s  += __shfl_xor_sync(0xffffffffu, s, m);
            s2 += __shfl_xor_sync(0xffffffffu, s2, m);
        }
        const float mu = s * 0.0078125f;
        const float rstd = rsqrtf(s2 * 0.0078125f - mu * mu + 1e-5f);
        u64t hA = pack2(fmaxf((a - mu) * rstd * gq.x + eq.x, 0.f),
                        fmaxf((b - mu) * rstd * gq.y + eq.y, 0.f));
        u64t hB = pack2(fmaxf((c - mu) * rstd * gq.z + eq.z, 0.f),
                        fmaxf((d - mu) * rstd * gq.w + eq.w, 0.f));
#pragma unroll
        for (int k = 0; k < 8; k++) { fma2(X20[k], uk[k], hA); fma2(X21[k], uk[k], hB); }
    }
#pragma unroll
    for (int k = 0; k < 8; k++) {
        float a, b, c, d;
        unpack2(X20[k], a, b); unpack2(X21[k], c, d);
        *(float4*)(sFX + (t * 8 + k) * 128 + 4 * lane) = make_float4(a, b, c, d);
    }
}

// Stage E, one warp = one tile: o = Um@F + b3 -> LN -> relu -> out = h@Wo + bo.
// v4 except Um dup pairs.
static __device__ __forceinline__ void tile_stageE(const float* sFX, const float* sUmD,
                                                   const float* sV, const u64t* sWoB,
                                                   float* __restrict__ outg,
                                                   int t, int lane)
{
    u64t Fr0[8], Fr1[8];
#pragma unroll
    for (int k = 0; k < 8; k++) {
        float4 f = *(const float4*)(sFX + (t * 8 + k) * 128 + 4 * lane);
        Fr0[k] = pack2(f.x, f.y); Fr1[k] = pack2(f.z, f.w);
    }
    const float4 bq = *(const float4*)(sV + 256 + 4 * lane);
    const float4 gq = *(const float4*)(sV + 640 + 4 * lane);
    const float4 eq = *(const float4*)(sV + 768 + 4 * lane);
    const u64t b01 = pack2(bq.x, bq.y), b23 = pack2(bq.z, bq.w);

    u64t w2[4][4];
    {
        const int l7 = lane & 7;
#pragma unroll
        for (int u = 0; u < 8; u++) {
            int p = lane * 8 + (u ^ l7);
            u64t A = sWoB[2 * p], B = sWoB[2 * p + 1];
            const int j = u >> 1, qb = (u & 1) * 2;
            w2[j][qb] = A; w2[j][qb + 1] = B;
        }
    }
    const int g = lane >> 3;
    float2 boP = *(const float2*)(sV + 896 + 2 * g);

#pragma unroll 2
    for (int n = 0; n < 64; n++) {
        ulonglong2 uA = *(const ulonglong2*)(sUmD + n * 16);
        ulonglong2 uB = *(const ulonglong2*)(sUmD + n * 16 + 4);
        ulonglong2 uC = *(const ulonglong2*)(sUmD + n * 16 + 8);
        ulonglong2 uD = *(const ulonglong2*)(sUmD + n * 16 + 12);
        u64t uk[8] = {uA.x, uA.y, uB.x, uB.y, uC.x, uC.y, uD.x, uD.y};
        u64t o0 = b01, o1 = b23;
#pragma unroll
        for (int k = 0; k < 8; k++) { fma2(o0, uk[k], Fr0[k]); fma2(o1, uk[k], Fr1[k]); }
        float a, b, c, d;
        unpack2(o0, a, b); unpack2(o1, c, d);
        float s = a + b + c + d;
        float s2 = a * a + b * b + c * c + d * d;
#pragma unroll
        for (int m = 1; m < 32; m <<= 1) {
            s  += __shfl_xor_sync(0xffffffffu, s, m);
            s2 += __shfl_xor_sync(0xffffffffu, s2, m);
        }
        const float mu = s * 0.0078125f;
        const float rstd = rsqrtf(s2 * 0.0078125f - mu * mu + 1e-5f);
        float h0 = fmaxf((a - mu) * rstd * gq.x + eq.x, 0.f);
        float h1 = fmaxf((b - mu) * rstd * gq.y + eq.y, 0.f);
        float h2 = fmaxf((c - mu) * rstd * gq.z + eq.z, 0.f);
        float h3 = fmaxf((d - mu) * rstd * gq.w + eq.w, 0.f);

        u64t acc2[4] = {0ull, 0ull, 0ull, 0ull};
        u64t hb;
        hb = dup2(h0);
#pragma unroll
        for (int q = 0; q < 4; q++) fma2(acc2[q], hb, w2[0][q]);
        hb = dup2(h1);
#pragma unroll
        for (int q = 0; q < 4; q++) fma2(acc2[q], hb, w2[1][q]);
        hb = dup2(h2);
#pragma unroll
        for (int q = 0; q < 4; q++) fma2(acc2[q], hb, w2[2][q]);
        hb = dup2(h3);
#pragma unroll
        for (int q = 0; q < 4; q++) fma2(acc2[q], hb, w2[3][q]);

#pragma unroll
        for (int q = 0; q < 4; q++)
            acc2[q] = add2(acc2[q], __shfl_xor_sync(0xffffffffu, acc2[q], 16));
#pragma unroll
        for (int q = 0; q < 4; q++)
            acc2[q] = add2(acc2[q], __shfl_xor_sync(0xffffffffu, acc2[q], 8));
        u64t v = (g == 0) ? acc2[0] : (g == 1) ? acc2[1] : (g == 2) ? acc2[2] : acc2[3];
        v = add2(v, __shfl_xor_sync(0xffffffffu, v, 4));
        v = add2(v, __shfl_xor_sync(0xffffffffu, v, 2));
        v = add2(v, __shfl_xor_sync(0xffffffffu, v, 1));
        if ((lane & 7) == (n & 7)) {
            float x, y; unpack2(v, x, y);
            *(float2*)(outg + n * 8 + 2 * g) = make_float2(x + boP.x, y + boP.y);
        }
    }
}

__global__ void __launch_bounds__(NT, 2)
main_kernel(const float* __restrict__ x, const float* __restrict__ U,
            const float* __restrict__ Wp, const float* __restrict__ bp,
            const float* __restrict__ g1, const float* __restrict__ be1,
            const float* __restrict__ g3, const float* __restrict__ be3,
            const float* __restrict__ Wo, const float* __restrict__ bo,
            float* __restrict__ out)
{
    extern __shared__ float sm[];
    float* sFX  = sm + O_FX;
    float* sUm  = sm + O_UM;
    float* sUmD = sm + O_UMD;
    float* sWp  = sm + O_WP;
    float* sV   = sm + O_V;
    float* sY   = sm + O_Y;
    u64t*  sWoB = (u64t*)(sm + O_WOB);

    const int tid = threadIdx.x;
    const int wid = tid >> 5, lane = tid & 31;

    // ---- init: weights/vectors ----
    if (tid < 64) {
#pragma unroll
        for (int k = 0; k < 8; k++) {
            float v = U[tid * 64 + k];
            sUm[tid * 8 + k] = v;
            sUmD[tid * 16 + 2 * k]     = v;
            sUmD[tid * 16 + 2 * k + 1] = v;
        }
    }
    for (int i = tid; i < 1024; i += NT) sWp[i] = Wp[i];
    if (tid < 128) {
        sV[tid]       = bp[tid];
        sV[128 + tid] = d_b1[tid];
        sV[256 + tid] = d_b3[tid];
        sV[384 + tid] = g1[tid];
        sV[512 + tid] = be1[tid];
        sV[640 + tid] = g3[tid];
        sV[768 + tid] = be3[tid];
    }
    if (tid < 8) { sV[896 + tid] = bo[tid]; sV[904 + tid] = d_tv[tid]; }
    if (tid < 256) {
        const int l = tid >> 3, u = (tid & 7) ^ (l & 7);
        const int j = u >> 1, qb = (u & 1) * 2;
        const int c = 4 * l + j;
        sWoB[2 * tid]     = pack2(Wo[c * 8 + 2 * qb],     Wo[c * 8 + 2 * qb + 1]);
        sWoB[2 * tid + 1] = pack2(Wo[c * 8 + 2 * qb + 2], Wo[c * 8 + 2 * qb + 3]);
    }
    __syncthreads();

    // ---- stage A pass 1: y[t][k][p] = sum_n Um[n,k] x[t][n][p] ----
    {
        const int k = lane >> 2, q = lane & 3;
        const float2* xg2 = (const float2*)(x + (size_t)blockIdx.x * 4096 + wid * 512);
        u64t acc = 0ull;
#pragma unroll 4
        for (int n = 0; n < 64; n++) {
            float um = sUm[n * 8 + k];
            float2 xv = __ldg(&xg2[n * 4 + q]);
            fma2(acc, dup2(um), pack2(xv.x, xv.y));
        }
        float a, b; unpack2(acc, a, b);
        *(float2*)(sY + wid * 64 + k * 8 + 2 * q) = make_float2(a, b);
    }
    __syncthreads();

    // ---- stage A pass 2: XF[t][k][c] = tv[k]*bp[c] + sum_p y[t][k][p] Wp[p][c] ----
    // warp k writes rows (t,k) -> consumed by the same warp in mode_gemm (no sync)
    {
        const int k = wid, c4 = lane;
        const float tvk = sV[904 + k];
        const float4 bp4 = ((const float4*)sV)[c4];
#pragma unroll
        for (int t = 0; t < TT; t++) {
            const float* yv = sY + t * 64 + k * 8;
            u64t a01 = 0ull, a23 = 0ull;
            u64t tb = dup2(tvk);
            fma2(a01, tb, pack2(bp4.x, bp4.y));
            fma2(a23, tb, pack2(bp4.z, bp4.w));
#pragma unroll
            for (int p = 0; p < 8; p++) {
                u64t yb = dup2(yv[p]);
                float4 wp = ((const float4*)(sWp + p * 128))[c4];
                fma2(a01, yb, pack2(wp.x, wp.y));
                fma2(a23, yb, pack2(wp.z, wp.w));
            }
            float a, b, c, d;
            unpack2(a01, a, b); unpack2(a23, c, d);
            *(float4*)(sFX + (t * 8 + k) * 128 + 4 * c4) = make_float4(a, b, c, d);
        }
    }

    // ---- stage B: f0 = per-mode GEMM with M0 (in place) ----
    mode_gemm(d_M0, sFX, tid);
    __syncthreads();

    // ---- stage C: warp w handles tile w entirely ----
    tile_stageC(sFX, sUmD, sV, wid, lane);
    __syncthreads();

    // ---- stage D: f2 = per-mode GEMM with M2 (in place) ----
    mode_gemm(d_M2, sFX, tid);
    __syncthreads();

    // ---- stage E: warp w handles tile w entirely, fused output projection ----
    float* outg = out + (size_t)blockIdx.x * 4096;
    tile_stageE(sFX, sUmD, sV, sWoB, outg + wid * 512, wid, lane);
}

// ------------------------------- launch ------------------------------------

extern "C" void kernel_launch(void* const* d_in, const int* in_sizes, int n_in,
                              void* d_out, int out_size)
{
    const float* x   = (const float*)d_in[0];
    const float* adj = (const float*)d_in[1];
    const float* U   = (const float*)d_in[2];
    const float* Wp  = (const float*)d_in[3];
    const float* bp  = (const float*)d_in[4];
    const float* w0  = (const float*)d_in[5];
    const float* w2  = (const float*)d_in[6];
    const float* Ws1 = (const float*)d_in[7];
    const float* bs1 = (const float*)d_in[8];
    const float* Wn1 = (const float*)d_in[9];
    const float* bn1 = (const float*)d_in[10];
    const float* g1  = (const float*)d_in[11];
    const float* be1 = (const float*)d_in[12];
    const float* Ws3 = (const float*)d_in[13];
    const float* bs3 = (const float*)d_in[14];
    const float* Wn3 = (const float*)d_in[15];
    const float* bn3 = (const float*)d_in[16];
    const float* g3  = (const float*)d_in[17];
    const float* be3 = (const float*)d_in[18];
    const float* Wo  = (const float*)d_in[19];
    const float* bo  = (const float*)d_in[20];
    float* out = (float*)d_out;

    pre_kernel<<<256, 128>>>(U, adj, w0, w2, Ws1, Wn1, Ws3, Wn3,
                             bs1, bn1, bs3, bn3);

    const size_t smem = SMEMF * sizeof(float);  // 52 KB -> 2 CTAs/SM (reg-bound)
    cudaFuncSetAttribute(main_kernel, cudaFuncAttributeMaxDynamicSharedMemorySize,
                         (int)smem);
    main_kernel<<<2048, NT, smem>>>(x, U, Wp, bp, g1, be1, g3, be3, Wo, bo, out);
}

// round 12
// speedup vs baseline: 1.1204x; 1.0508x over previous
#include <cuda_runtime.h>

// ---------------------------------------------------------------------------
// Model_19095424598065 v12 : algebraically reduced graph-spectral net.
// Consolidation: R4 main kernel EXACTLY (best measured, 544us kernel;
// every hand-modification since has regressed it) + fused single
// pre_kernel (bench-vs-kernel gap 93us -> ~4us). Nothing else.
// ---------------------------------------------------------------------------

typedef unsigned long long u64t;

#define NT 256
#define TT 8

__device__ float d_M0[8 * 128 * 128];   // scalar layout [k][i][c]
__device__ float d_M2[8 * 128 * 128];
__device__ float d_tv[8];
__device__ float d_b1[128];
__device__ float d_b3[128];

// ------------------------------ helpers ------------------------------------
static __device__ __forceinline__ u64t dup2(float x) {
    u64t r; asm("mov.b64 %0, {%1, %1};" : "=l"(r) : "f"(x)); return r;
}
static __device__ __forceinline__ u64t pack2(float a, float b) {
    u64t r; asm("mov.b64 %0, {%1, %2};" : "=l"(r) : "f"(a), "f"(b)); return r;
}
static __device__ __forceinline__ void unpack2(u64t v, float& a, float& b) {
    asm("mov.b64 {%0, %1}, %2;" : "=f"(a), "=f"(b) : "l"(v));
}
static __device__ __forceinline__ void fma2(u64t& d, u64t a, u64t b) {
    asm("fma.rn.f32x2 %0, %1, %2, %3;" : "=l"(d) : "l"(a), "l"(b), "l"(d));
}
static __device__ __forceinline__ u64t add2(u64t a, u64t b) {
    u64t r; asm("add.rn.f32x2 %0, %1, %2;" : "=l"(r) : "l"(a), "l"(b)); return r;
}

// --------------------------- fused precompute ------------------------------
// 256 blocks: b<128 -> M0 row b; b>=128 -> M2 row b-128. lam computed locally.
__global__ void pre_kernel(const float* __restrict__ U, const float* __restrict__ adj,
                           const float* __restrict__ w0, const float* __restrict__ w2,
                           const float* __restrict__ Ws1, const float* __restrict__ Wn1,
                           const float* __restrict__ Ws3, const float* __restrict__ Wn3,
                           const float* __restrict__ bs1, const float* __restrict__ bn1,
                           const float* __restrict__ bs3, const float* __restrict__ bn3)
{
    __shared__ float sw[1024];
    __shared__ float spart[128];
    __shared__ float slam[8];
    const int b = blockIdx.x, c = threadIdx.x;
    const int which = b >> 7, i = b & 127;
    const float* w  = which ? w2  : w0;
    const float* Ws = which ? Ws3 : Ws1;
    const float* Wn = which ? Wn3 : Wn1;

    {
        const int k = c >> 4, s = c & 15;
        float part = 0.f;
        for (int n = s; n < 64; n += 16) {
            float g = 0.f;
            for (int m = 0; m < 64; m++) g += adj[n * 64 + m] * U[m * 64 + k];
            part += U[n * 64 + k] * g;
        }
        spart[c] = part;
    }
    for (int idx = c; idx < 1024; idx += 128) sw[idx] = w[i * 1024 + idx];
    __syncthreads();
    if (c < 8) {
        float lam = 0.f;
        for (int s = 0; s < 16; s++) lam += spart[c * 16 + s];
        slam[c] = lam;
    }
    if (b == 0) {
        if (c < 128) { d_b1[c] = bs1[c] + bn1[c]; d_b3[c] = bs3[c] + bn3[c]; }
        if (c < 8) {
            float ts = 0.f;
            for (int n = 0; n < 64; n++) ts += U[n * 64 + c];
            d_tv[c] = ts;
        }
    }
    __syncthreads();

    float lam[8], acc[8];
#pragma unroll
    for (int k = 0; k < 8; k++) { lam[k] = slam[k]; acc[k] = 0.f; }
#pragma unroll 2
    for (int j = 0; j < 128; j++) {
        float ws = __ldg(Ws + j * 128 + c);
        float wn = __ldg(Wn + j * 128 + c);
#pragma unroll
        for (int k = 0; k < 8; k++)
            acc[k] += sw[j * 8 + k] * fmaf(lam[k], wn, ws);
    }
    float* M = which ? d_M2 : d_M0;
#pragma unroll
    for (int k = 0; k < 8; k++) M[(k * 128 + i) * 128 + c] = acc[k];
}

// ------------------------------- main kernel (R4 verbatim) -----------------
// smem (floats):
//  sFX  [0    , 8192 )  XF/F in place [t][k][c]
//  sUm  [8192 , 8704 )  Um[n][k] stride 8
//  sWp  [8704 , 9728 )  Wp[p][c]
//  sV   [9728 , 10752)  bp|b1|b3|g1|be1|g3|be3|bo(8)|tv(8)
//  sY   [10752, 11264)  stage-A y[t][k][p]
//  sWoB [11264, 12288)  Wo pairs, per-lane swizzled (512 u64)
#define O_FX  0
#define O_UM  8192
#define O_WP  8704
#define O_V   9728
#define O_Y   10752
#define O_WOB 11264
#define SMEMF 12288

// F[t,k,:] = XF[t,k,:] @ M_k (K=128), in place. Warp k owns mode k's rows.
static __device__ __forceinline__ void mode_gemm(const float* __restrict__ M,
                                                 float* sFX, int tid)
{
    const int k = tid >> 5, lane = tid & 31;
    const float4* Mk4 = (const float4*)(M + k * 16384);
    u64t a01[TT], a23[TT];
#pragma unroll
    for (int t = 0; t < TT; t++) { a01[t] = 0ull; a23[t] = 0ull; }

#pragma unroll 2
    for (int i4 = 0; i4 < 32; i4++) {
        float4 xv[TT];
#pragma unroll
        for (int t = 0; t < TT; t++)  // uniform address -> broadcast, 1 wf
            xv[t] = *(const float4*)(sFX + (t * 8 + k) * 128 + 4 * i4);
#pragma unroll
        for (int ii = 0; ii < 4; ii++) {
            float4 m = __ldg(&Mk4[(4 * i4 + ii) * 32 + lane]);
            u64t m01 = pack2(m.x, m.y), m23 = pack2(m.z, m.w);
#pragma unroll
            for (int t = 0; t < TT; t++) {
                float xs = (ii == 0) ? xv[t].x : (ii == 1) ? xv[t].y
                         : (ii == 2) ? xv[t].z : xv[t].w;
                u64t xb = dup2(xs);
                fma2(a01[t], xb, m01);
                fma2(a23[t], xb, m23);
            }
        }
    }
#pragma unroll
    for (int t = 0; t < TT; t++) {
        float a, b, c, d;
        unpack2(a01[t], a, b); unpack2(a23[t], c, d);
        *(float4*)(sFX + (t * 8 + k) * 128 + 4 * lane) = make_float4(a, b, c, d);
    }
}

// Stage C, one warp = one tile t: o = Um@F + b1 -> LN -> relu -> xf2 = Um^T h,
// xf2 accumulated in registers, written back into sFX rows (t,k).
static __device__ __forceinline__ void tile_stageC(float* sFX, const float* sUm,
                                                   const float* sV, int t, int lane)
{
    u64t Fr0[8], Fr1[8];
#pragma unroll
    for (int k = 0; k < 8; k++) {
        float4 f = *(const float4*)(sFX + (t * 8 + k) * 128 + 4 * lane);
        Fr0[k] = pack2(f.x, f.y); Fr1[k] = pack2(f.z, f.w);
    }
    const float4 bq = *(const float4*)(sV + 128 + 4 * lane);
    const float4 gq = *(const float4*)(sV + 384 + 4 * lane);
    const float4 eq = *(const float4*)(sV + 512 + 4 * lane);
    const u64t b01 = pack2(bq.x, bq.y), b23 = pack2(bq.z, bq.w);

    u64t X20[8], X21[8];
#pragma unroll
    for (int k = 0; k < 8; k++) { X20[k] = 0ull; X21[k] = 0ull; }

#pragma unroll 4
    for (int n = 0; n < 64; n++) {
        float4 u0 = *(const float4*)(sUm + n * 8);      // uniform -> broadcast
        float4 u1 = *(const float4*)(sUm + n * 8 + 4);
        u64t uk[8] = {dup2(u0.x), dup2(u0.y), dup2(u0.z), dup2(u0.w),
                      dup2(u1.x), dup2(u1.y), dup2(u1.z), dup2(u1.w)};
        u64t o0 = b01, o1 = b23;
#pragma unroll
        for (int k = 0; k < 8; k++) { fma2(o0, uk[k], Fr0[k]); fma2(o1, uk[k], Fr1[k]); }
        float a, b, c, d;
        unpack2(o0, a, b); unpack2(o1, c, d);
        float s = a + b + c + d;
        float s2 = a * a + b * b + c * c + d * d;
#pragma unroll
        for (int m = 1; m < 32; m <<= 1) {
            s  += __shfl_xor_sync(0xffffffffu, s, m);
            s2 += __shfl_xor_sync(0xffffffffu, s2, m);
        }
        const float mu = s * 0.0078125f;
        const float rstd = rsqrtf(s2 * 0.0078125f - mu * mu + 1e-5f);
        u64t hA = pack2(fmaxf((a - mu) * rstd * gq.x + eq.x, 0.f),
                        fmaxf((b - mu) * rstd * gq.y + eq.y, 0.f));
        u64t hB = pack2(fmaxf((c - mu) * rstd * gq.z + eq.z, 0.f),
                        fmaxf((d - mu) * rstd * gq.w + eq.w, 0.f));
#pragma unroll
        for (int k = 0; k < 8; k++) { fma2(X20[k], uk[k], hA); fma2(X21[k], uk[k], hB); }
    }
#pragma unroll
    for (int k = 0; k < 8; k++) {
        float a, b, c, d;
        unpack2(X20[k], a, b); unpack2(X21[k], c, d);
        *(float4*)(sFX + (t * 8 + k) * 128 + 4 * lane) = make_float4(a, b, c, d);
    }
}

// Stage E, one warp = one tile: o = Um@F + b3 -> LN -> relu -> out = h@Wo + bo.
// Wo held in per-lane registers (swizzled smem load); butterfly reductions;
// 2-lane predicated STG per node.
static __device__ __forceinline__ void tile_stageE(const float* sFX, const float* sUm,
                                                   const float* sV, const u64t* sWoB,
                                                   float* __restrict__ outg,
                                                   int t, int lane)
{
    u64t Fr0[8], Fr1[8];
#pragma unroll
    for (int k = 0; k < 8; k++) {
        float4 f = *(const float4*)(sFX + (t * 8 + k) * 128 + 4 * lane);
        Fr0[k] = pack2(f.x, f.y); Fr1[k] = pack2(f.z, f.w);
    }
    const float4 bq = *(const float4*)(sV + 256 + 4 * lane);
    const float4 gq = *(const float4*)(sV + 640 + 4 * lane);
    const float4 eq = *(const float4*)(sV + 768 + 4 * lane);
    const u64t b01 = pack2(bq.x, bq.y), b23 = pack2(bq.z, bq.w);

    u64t w2[4][4];
    {
        const int l7 = lane & 7;
#pragma unroll
        for (int u = 0; u < 8; u++) {
            int p = lane * 8 + (u ^ l7);
            u64t A = sWoB[2 * p], B = sWoB[2 * p + 1];
            const int j = u >> 1, qb = (u & 1) * 2;
            w2[j][qb] = A; w2[j][qb + 1] = B;
        }
    }
    const int g = lane >> 3;
    float2 boP = *(const float2*)(sV + 896 + 2 * g);

#pragma unroll 2
    for (int n = 0; n < 64; n++) {
        float4 u0 = *(const float4*)(sUm + n * 8);
        float4 u1 = *(const float4*)(sUm + n * 8 + 4);
        u64t uk[8] = {dup2(u0.x), dup2(u0.y), dup2(u0.z), dup2(u0.w),
                      dup2(u1.x), dup2(u1.y), dup2(u1.z), dup2(u1.w)};
        u64t o0 = b01, o1 = b23;
#pragma unroll
        for (int k = 0; k < 8; k++) { fma2(o0, uk[k], Fr0[k]); fma2(o1, uk[k], Fr1[k]); }
        float a, b, c, d;
        unpack2(o0, a, b); unpack2(o1, c, d);
        float s = a + b + c + d;
        float s2 = a * a + b * b + c * c + d * d;
#pragma unroll
        for (int m = 1; m < 32; m <<= 1) {
            s  += __shfl_xor_sync(0xffffffffu, s, m);
            s2 += __shfl_xor_sync(0xffffffffu, s2, m);
        }
        const float mu = s * 0.0078125f;
        const float rstd = rsqrtf(s2 * 0.0078125f - mu * mu + 1e-5f);
        float h0 = fmaxf((a - mu) * rstd * gq.x + eq.x, 0.f);
        float h1 = fmaxf((b - mu) * rstd * gq.y + eq.y, 0.f);
        float h2 = fmaxf((c - mu) * rstd * gq.z + eq.z, 0.f);
        float h3 = fmaxf((d - mu) * rstd * gq.w + eq.w, 0.f);

        u64t acc2[4] = {0ull, 0ull, 0ull, 0ull};
        u64t hb;
        hb = dup2(h0);
#pragma unroll
        for (int q = 0; q < 4; q++) fma2(acc2[q], hb, w2[0][q]);
        hb = dup2(h1);
#pragma unroll
        for (int q = 0; q < 4; q++) fma2(acc2[q], hb, w2[1][q]);
        hb = dup2(h2);
#pragma unroll
        for (int q = 0; q < 4; q++) fma2(acc2[q], hb, w2[2][q]);
        hb = dup2(h3);
#pragma unroll
        for (int q = 0; q < 4; q++) fma2(acc2[q], hb, w2[3][q]);

#pragma unroll
        for (int q = 0; q < 4; q++)
            acc2[q] = add2(acc2[q], __shfl_xor_sync(0xffffffffu, acc2[q], 16));
#pragma unroll
        for (int q = 0; q < 4; q++)
            acc2[q] = add2(acc2[q], __shfl_xor_sync(0xffffffffu, acc2[q], 8));
        u64t v = (g == 0) ? acc2[0] : (g == 1) ? acc2[1] : (g == 2) ? acc2[2] : acc2[3];
        v = add2(v, __shfl_xor_sync(0xffffffffu, v, 4));
        v = add2(v, __shfl_xor_sync(0xffffffffu, v, 2));
        v = add2(v, __shfl_xor_sync(0xffffffffu, v, 1));
        if ((lane & 7) == (n & 7)) {
            float x, y; unpack2(v, x, y);
            *(float2*)(outg + n * 8 + 2 * g) = make_float2(x + boP.x, y + boP.y);
        }
    }
}

__global__ void __launch_bounds__(NT, 2)
main_kernel(const float* __restrict__ x, const float* __restrict__ U,
            const float* __restrict__ Wp, const float* __restrict__ bp,
            const float* __restrict__ g1, const float* __restrict__ be1,
            const float* __restrict__ g3, const float* __restrict__ be3,
            const float* __restrict__ Wo, const float* __restrict__ bo,
            float* __restrict__ out)
{
    extern __shared__ float sm[];
    float* sFX  = sm + O_FX;
    float* sUm  = sm + O_UM;
    float* sWp  = sm + O_WP;
    float* sV   = sm + O_V;
    float* sY   = sm + O_Y;
    u64t*  sWoB = (u64t*)(sm + O_WOB);

    const int tid = threadIdx.x;
    const int wid = tid >> 5, lane = tid & 31;

    // ---- init: weights/vectors ----
    if (tid < 64) {
#pragma unroll
        for (int k = 0; k < 8; k++) sUm[tid * 8 + k] = U[tid * 64 + k];
    }
    for (int i = tid; i < 1024; i += NT) sWp[i] = Wp[i];
    if (tid < 128) {
        sV[tid]       = bp[tid];
        sV[128 + tid] = d_b1[tid];
        sV[256 + tid] = d_b3[tid];
        sV[384 + tid] = g1[tid];
        sV[512 + tid] = be1[tid];
        sV[640 + tid] = g3[tid];
        sV[768 + tid] = be3[tid];
    }
    if (tid < 8) { sV[896 + tid] = bo[tid]; sV[904 + tid] = d_tv[tid]; }
    if (tid < 256) {
        const int l = tid >> 3, u = (tid & 7) ^ (l & 7);
        const int j = u >> 1, qb = (u & 1) * 2;
        const int c = 4 * l + j;
        sWoB[2 * tid]     = pack2(Wo[c * 8 + 2 * qb],     Wo[c * 8 + 2 * qb + 1]);
        sWoB[2 * tid + 1] = pack2(Wo[c * 8 + 2 * qb + 2], Wo[c * 8 + 2 * qb + 3]);
    }
    __syncthreads();

    // ---- stage A pass 1: y[t][k][p] = sum_n Um[n,k] x[t][n][p] ----
    {
        const int k = lane >> 2, q = lane & 3;
        const float2* xg2 = (const float2*)(x + (size_t)blockIdx.x * 4096 + wid * 512);
        u64t acc = 0ull;
#pragma unroll 4
        for (int n = 0; n < 64; n++) {
            float um = sUm[n * 8 + k];
            float2 xv = __ldg(&xg2[n * 4 + q]);
            fma2(acc, dup2(um), pack2(xv.x, xv.y));
        }
        float a, b; unpack2(acc, a, b);
        *(float2*)(sY + wid * 64 + k * 8 + 2 * q) = make_float2(a, b);
    }
    __syncthreads();

    // ---- stage A pass 2: XF[t][k][c] = tv[k]*bp[c] + sum_p y[t][k][p] Wp[p][c] ----
    // warp k writes rows (t,k) -> consumed by the same warp in mode_gemm (no sync)
    {
        const int k = wid, c4 = lane;
        const float tvk = sV[904 + k];
        const float4 bp4 = ((const float4*)sV)[c4];
#pragma unroll
        for (int t = 0; t < TT; t++) {
            const float* yv = sY + t * 64 + k * 8;
            u64t a01 = 0ull, a23 = 0ull;
            u64t tb = dup2(tvk);
            fma2(a01, tb, pack2(bp4.x, bp4.y));
            fma2(a23, tb, pack2(bp4.z, bp4.w));
#pragma unroll
            for (int p = 0; p < 8; p++) {
                u64t yb = dup2(yv[p]);
                float4 wp = ((const float4*)(sWp + p * 128))[c4];
                fma2(a01, yb, pack2(wp.x, wp.y));
                fma2(a23, yb, pack2(wp.z, wp.w));
            }
            float a, b, c, d;
            unpack2(a01, a, b); unpack2(a23, c, d);
            *(float4*)(sFX + (t * 8 + k) * 128 + 4 * c4) = make_float4(a, b, c, d);
        }
    }

    // ---- stage B: f0 = per-mode GEMM with M0 (in place) ----
    mode_gemm(d_M0, sFX, tid);
    __syncthreads();

    // ---- stage C: warp w handles tile w entirely ----
    tile_stageC(sFX, sUm, sV, wid, lane);
    __syncthreads();

    // ---- stage D: f2 = per-mode GEMM with M2 (in place) ----
    mode_gemm(d_M2, sFX, tid);
    __syncthreads();

    // ---- stage E: warp w handles tile w entirely, fused output projection ----
    float* outg = out + (size_t)blockIdx.x * 4096;
    tile_stageE(sFX, sUm, sV, sWoB, outg + wid * 512, wid, lane);
}

// ------------------------------- launch ------------------------------------

extern "C" void kernel_launch(void* const* d_in, const int* in_sizes, int n_in,
                              void* d_out, int out_size)
{
    const float* x   = (const float*)d_in[0];
    const float* adj = (const float*)d_in[1];
    const float* U   = (const float*)d_in[2];
    const float* Wp  = (const float*)d_in[3];
    const float* bp  = (const float*)d_in[4];
    const float* w0  = (const float*)d_in[5];
    const float* w2  = (const float*)d_in[6];
    const float* Ws1 = (const float*)d_in[7];
    const float* bs1 = (const float*)d_in[8];
    const float* Wn1 = (const float*)d_in[9];
    const float* bn1 = (const float*)d_in[10];
    const float* g1  = (const float*)d_in[11];
    const float* be1 = (const float*)d_in[12];
    const float* Ws3 = (const float*)d_in[13];
    const float* bs3 = (const float*)d_in[14];
    const float* Wn3 = (const float*)d_in[15];
    const float* bn3 = (const float*)d_in[16];
    const float* g3  = (const float*)d_in[17];
    const float* be3 = (const float*)d_in[18];
    const float* Wo  = (const float*)d_in[19];
    const float* bo  = (const float*)d_in[20];
    float* out = (float*)d_out;

    pre_kernel<<<256, 128>>>(U, adj, w0, w2, Ws1, Wn1, Ws3, Wn3,
                             bs1, bn1, bs3, bn3);

    const size_t smem = SMEMF * sizeof(float);  // 48 KB -> 2 CTAs/SM
    cudaFuncSetAttribute(main_kernel, cudaFuncAttributeMaxDynamicSharedMemorySize,
                         (int)smem);
    main_kernel<<<2048, NT, smem>>>(x, U, Wp, bp, g1, be1, g3, be3, Wo, bo, out);
}